// round 15
// baseline (speedup 1.0000x reference)
#include <cuda_runtime.h>
#include <cuda_fp16.h>
#include <cstdint>

// Problem constants
#define BB   8
#define CC   256
#define HH   128
#define WW   128
#define GG   8       // ska groups (32 ch each)
#define NPIX 16384   // H*W
#define EPSV 1e-5f
#define HP   130     // spatially padded dim (1-px zero border)

// Scratch (device globals; allocation-free rule). Zero-initialized at load:
// g_ska2h's 1-pixel spatial border is never written -> stays zero (implicit pad).
__device__ float  g_ska[BB * CC * NPIX];                // raw SKA output (residual), planar fp32
__device__ __half g_ska2h[BB * GG * HP * HP * 32];      // ska*roi, channel-last, padded, fp16
__device__ __half g_t2h[BB * NPIX * CC];                // conv3 out, [b][pix][ci], fp16
__device__ __half g_w1h[GG * 9 * 32 * 32];              // w1*s1, [g][tap][co][cin], fp16
__device__ __half g_w2h[CC * CC];                       // w2*s2, [co][ci], fp16
__device__ float  g_s1[CC], g_bb1[CC], g_s2[CC], g_bb2[CC];

// ---------- cp.async helpers ----------
__device__ __forceinline__ void cp16(uint32_t dst, const void* src) {
    asm volatile("cp.async.cg.shared.global [%0], [%1], 16;" :: "r"(dst), "l"(src));
}
__device__ __forceinline__ void cp_commit() {
    asm volatile("cp.async.commit_group;");
}
__device__ __forceinline__ void cp_wait1() {
    asm volatile("cp.async.wait_group 1;");
}
__device__ __forceinline__ void cp_wait0() {
    asm volatile("cp.async.wait_group 0;");
}

__device__ __forceinline__ uint32_t smem_u32(const void* p) {
    uint32_t a;
    asm("{ .reg .u64 t; cvta.to.shared.u64 t, %1; cvt.u32.u64 %0, t; }" : "=r"(a) : "l"(p));
    return a;
}

__device__ __forceinline__ uint32_t h2bits(float a, float b) {
    __half2 h = __floats2half2_rn(a, b);
    return *reinterpret_cast<uint32_t*>(&h);
}

// ---------- mma.sync m16n8k16 fp16, fp32 accum ----------
__device__ __forceinline__ void mma16(float* c, const uint32_t* a, const uint32_t* b) {
    asm volatile(
        "mma.sync.aligned.m16n8k16.row.col.f32.f16.f16.f32 "
        "{%0,%1,%2,%3}, {%4,%5,%6,%7}, {%8,%9}, {%0,%1,%2,%3};"
        : "+f"(c[0]), "+f"(c[1]), "+f"(c[2]), "+f"(c[3])
        : "r"(a[0]), "r"(a[1]), "r"(a[2]), "r"(a[3]), "r"(b[0]), "r"(b[1]));
}

// ---------- ldmatrix x4 (b16, non-transposed) ----------
__device__ __forceinline__ void ldsm4(uint32_t* r, uint32_t addr) {
    asm volatile("ldmatrix.sync.aligned.m8n8.x4.shared.b16 {%0,%1,%2,%3}, [%4];"
                 : "=r"(r[0]), "=r"(r[1]), "=r"(r[2]), "=r"(r[3]) : "r"(addr));
}

// ---------- prep: fold BN params ----------
__global__ void prep_bn(const float* __restrict__ g1, const float* __restrict__ b1,
                        const float* __restrict__ m1, const float* __restrict__ v1,
                        const float* __restrict__ g2, const float* __restrict__ b2,
                        const float* __restrict__ m2, const float* __restrict__ v2) {
    int c = threadIdx.x;
    if (c < CC) {
        float i1 = g1[c] * rsqrtf(v1[c] + EPSV);
        g_s1[c]  = i1;
        g_bb1[c] = b1[c] - m1[c] * i1;
        float i2 = g2[c] * rsqrtf(v2[c] + EPSV);
        g_s2[c]  = i2;
        g_bb2[c] = b2[c] - m2[c] * i2;
    }
}

// ---------- prep: fold s1 into w1, fp16, [g][tap][co][cin] ----------
__global__ void prep_w1h(const float* __restrict__ w1) {
    int id = blockIdx.x * 256 + threadIdx.x;      // 73728 total
    int g  = id / 9216;
    int r  = id - g * 9216;
    int co = r / 288;
    int k  = r - co * 288;                        // cin*9 + tap
    int cin = k / 9, tap = k - cin * 9;
    g_w1h[g * 9216 + (tap * 32 + co) * 32 + cin] =
        __float2half_rn(w1[id] * g_s1[g * 32 + co]);
}

// ---------- prep: fold s2 into w2, fp16, [co][ci] ----------
__global__ void prep_w2h(const float* __restrict__ w2) {
    int i  = blockIdx.x * 256 + threadIdx.x;      // 65536 total
    g_w2h[i] = __float2half_rn(w2[i] * g_s2[i >> 8]);
}

// ---------- SKA: spatially-varying 3x3 aggregation ----------
// grid (H/2, B*G), block 256: 2 output rows. Register-prefetch + double-buffered
// smem rows -> ONE sync per channel, LDG latency hidden behind compute.
__global__ void ska_kernel(const float* __restrict__ x, const float* __restrict__ dw,
                           const float* __restrict__ roi) {
    __shared__ float rows[2][4][130];
    int h0 = blockIdx.x * 2;
    int bg = blockIdx.y;                 // b*G + g
    int b  = bg >> 3, g = bg & 7;
    int tid = threadIdx.x;
    int hr = tid >> 7;                   // 0/1: which output row
    int w  = tid & 127;

    if (tid < 16) {                      // zero halo cols, both buffers
        int bf = tid >> 3, r = (tid >> 1) & 3, s = tid & 1;
        rows[bf][r][s * 129] = 0.f;
    }

    int h = h0 + hr;
    float dwv[9];
    const float* dp = dw + (size_t)bg * 9 * NPIX + h * WW + w;
#pragma unroll
    for (int k = 0; k < 9; ++k) dwv[k] = dp[k * NPIX];

    float rv = roi[b * NPIX + h * WW + w];

    const float* xb = x + (size_t)(b * CC + g * 32) * NPIX;
    float* ob = g_ska + (size_t)(b * CC + g * 32) * NPIX + h * WW + w;

    // this thread stages rows j0, j1 of the 4-row window
    int j0 = hr * 2, j1 = hr * 2 + 1;
    int hh0 = h0 - 1 + j0, hh1 = h0 - 1 + j1;
    bool in0 = (unsigned)hh0 < (unsigned)HH;
    bool in1 = (unsigned)hh1 < (unsigned)HH;
    const float* xr0 = xb + (size_t)(in0 ? hh0 : 0) * WW + w;
    const float* xr1 = xb + (size_t)(in1 ? hh1 : 0) * WW + w;

    // prologue: stage channel 0 into buffer 0
    rows[0][j0][w + 1] = in0 ? xr0[0] : 0.f;
    rows[0][j1][w + 1] = in1 ? xr1[0] : 0.f;
    __syncthreads();

    float vals[32];
#pragma unroll
    for (int c = 0; c < 32; ++c) {
        int buf = c & 1;
        // prefetch channel c+1 (LDG issued before compute -> latency hidden)
        float n0 = 0.f, n1 = 0.f;
        if (c + 1 < 32) {
            size_t off = (size_t)(c + 1) * NPIX;
            if (in0) n0 = xr0[off];
            if (in1) n1 = xr1[off];
        }
        float acc = 0.f;
#pragma unroll
        for (int r = 0; r < 3; ++r)
#pragma unroll
            for (int kw = 0; kw < 3; ++kw)
                acc = fmaf(rows[buf][hr + r][w + kw], dwv[r * 3 + kw], acc);
        ob[(size_t)c * NPIX] = acc;
        vals[c] = acc * rv;
        if (c + 1 < 32) {
            rows[buf ^ 1][j0][w + 1] = n0;
            rows[buf ^ 1][j1][w + 1] = n1;
        }
        __syncthreads();
    }

    // channel-last padded fp16 write (interior only; border stays zero)
    __half* o = g_ska2h + (((size_t)bg * HP + h + 1) * HP + (w + 1)) * 32;
    uint32_t pk[16];
#pragma unroll
    for (int t = 0; t < 16; ++t) pk[t] = h2bits(vals[2 * t], vals[2 * t + 1]);
#pragma unroll
    for (int t = 0; t < 4; ++t)
        ((uint4*)o)[t] = make_uint4(pk[t * 4], pk[t * 4 + 1], pk[t * 4 + 2], pk[t * 4 + 3]);
}

// ---------- grouped 3x3 conv: mma.sync fp16 + ldmatrix + BN + ReLU ----------
// grid (8,8,64): CTA = 16x16 pixel tile, one (b, group). K=288 fully smem-resident.
// 8 warps: warp = 2 pixel rows x 32 couts (2 mt x 4 nt), K=16/MMA.
// smem (halves, stride 40/row = 80B, conflict-free for ldmatrix 8-row phases).
#define C3_TS     40                              // halves per pixel row (pad 32->40)
#define C3_TILE_H (324 * C3_TS)                   // 12960 halves
#define C3_WT_H   (288 * C3_TS)                   // 11520 halves
#define C3_SMEM   ((C3_TILE_H + C3_WT_H) * 2)     // 48960 B

__global__ void __launch_bounds__(256, 3)
conv3_mma() {
    extern __shared__ __half hsm[];
    __half* tile = hsm;                  // [pix(18x18)][40]
    __half* wt   = hsm + C3_TILE_H;      // [tap*32+co][40]

    int bz  = blockIdx.z;
    int b   = bz >> 3, g = bz & 7;
    int px0 = blockIdx.x * 16, py0 = blockIdx.y * 16;
    int tid = threadIdx.x;
    int wid = tid >> 5, lane = tid & 31;
    int rr  = lane >> 2, q = lane & 3;

    // stage input tile: 324 px x 64B = 1296 chunks of 16B
    {
        const __half* sbase = g_ska2h + (((size_t)(b * GG + g) * HP + py0) * HP + px0) * 32;
        uint32_t ts = smem_u32(tile);
        for (int ch = tid; ch < 1296; ch += 256) {
            int pix = ch >> 2, c4 = ch & 3;
            int r = pix / 18, c = pix - r * 18;
            cp16(ts + (uint32_t)(pix * (C3_TS * 2) + c4 * 16),
                 sbase + ((size_t)r * HP + c) * 32 + c4 * 8);
        }
        // stage weights: 288 rows x 64B = 1152 chunks
        const __half* wsrc = g_w1h + g * 9216;
        uint32_t ws = smem_u32(wt);
        for (int ch = tid; ch < 1152; ch += 256) {
            int row = ch >> 2, c4 = ch & 3;
            cp16(ws + (uint32_t)(row * (C3_TS * 2) + c4 * 16),
                 wsrc + row * 32 + c4 * 8);
        }
        cp_commit();
    }

    // ldmatrix per-lane bases
    // A: lanes 0-15 -> m-rows (pixel cols) @k0; lanes 16-31 -> same rows @k0+16B
    uint32_t a_lbase = smem_u32(tile) + (uint32_t)((lane & 15) * (C3_TS * 2) + (lane >> 4) * 16);
    // B: lanes 0-7 -> co 0-7 @k0; 8-15 -> co 0-7 @k0+16B; 16-23 -> co 8-15 @k0; 24-31 -> co 8-15 @k0+16B
    int brow = ((lane >> 4) & 1) * 8 + (lane & 7);
    uint32_t b_lbase = smem_u32(wt) + (uint32_t)(brow * (C3_TS * 2) + ((lane >> 3) & 1) * 16);

    float acc[2][4][4];
#pragma unroll
    for (int mt = 0; mt < 2; ++mt)
#pragma unroll
        for (int nt = 0; nt < 4; ++nt)
#pragma unroll
            for (int i = 0; i < 4; ++i) acc[mt][nt][i] = 0.f;

    cp_wait0();
    __syncthreads();

#pragma unroll
    for (int tap = 0; tap < 9; ++tap) {
        int kh = tap / 3, kw = tap - kh * 3;
#pragma unroll
        for (int k16 = 0; k16 < 2; ++k16) {
            uint32_t kofs = (uint32_t)(k16 * 32);          // 16 halves = 32B
            uint32_t afr[2][4];
#pragma unroll
            for (int mt = 0; mt < 2; ++mt)
                ldsm4(afr[mt], a_lbase + (uint32_t)(((wid * 2 + mt + kh) * 18 + kw) * (C3_TS * 2)) + kofs);
            uint32_t bfr[2][4];   // [g16]: {nt0.b0, nt0.b1, nt1.b0, nt1.b1}
#pragma unroll
            for (int g16 = 0; g16 < 2; ++g16)
                ldsm4(bfr[g16], b_lbase + (uint32_t)((tap * 32 + g16 * 16) * (C3_TS * 2)) + kofs);
#pragma unroll
            for (int mt = 0; mt < 2; ++mt)
#pragma unroll
                for (int nt = 0; nt < 4; ++nt)
                    mma16(acc[mt][nt], afr[mt], &bfr[nt >> 1][(nt & 1) * 2]);
        }
    }

    // epilogue: BN + ReLU, transpose via smem -> coalesced fp16 channel-last STG
    __syncthreads();                     // mainloop reads of tile/wt done
    float* buf = (float*)hsm;            // [co(32)][pix stride 260] = 33280 B
    int j0 = q * 2;
#pragma unroll
    for (int mt = 0; mt < 2; ++mt) {
        int lp0 = (wid * 2 + mt) * 16 + rr;
#pragma unroll
        for (int nt = 0; nt < 4; ++nt) {
            int co = nt * 8 + j0;
            float bbA = g_bb1[g * 32 + co], bbB = g_bb1[g * 32 + co + 1];
            buf[co * 260 + lp0]           = fmaxf(acc[mt][nt][0] + bbA, 0.f);
            buf[(co + 1) * 260 + lp0]     = fmaxf(acc[mt][nt][1] + bbB, 0.f);
            buf[co * 260 + lp0 + 8]       = fmaxf(acc[mt][nt][2] + bbA, 0.f);
            buf[(co + 1) * 260 + lp0 + 8] = fmaxf(acc[mt][nt][3] + bbB, 0.f);
        }
    }
    __syncthreads();
    {
        int lp = tid;                    // local pixel 0..255
        int gp = (py0 + (lp >> 4)) * WW + px0 + (lp & 15);
        __half* o = g_t2h + ((size_t)b * NPIX + gp) * CC + g * 32;
        uint32_t pk[16];
#pragma unroll
        for (int t = 0; t < 16; ++t)
            pk[t] = h2bits(buf[(2 * t) * 260 + lp], buf[(2 * t + 1) * 260 + lp]);
#pragma unroll
        for (int t = 0; t < 4; ++t)
            ((uint4*)o)[t] = make_uint4(pk[t * 4], pk[t * 4 + 1], pk[t * 4 + 2], pk[t * 4 + 3]);
    }
}

// ---------- 1x1 conv: mma.sync fp16 GEMM + ldmatrix + BN + residual ----------
// grid (128, 2, B): block = 128 pix x 128 co, K=256 (8 cp.async chunks of 32).
// 8 warps: warp = 32 pix x 64 co = 2 mt x 8 nt, K=16/MMA.
#define X1_TS   40
#define X1_OPH  (128 * X1_TS)            // halves per buf per operand
#define SM1X1   67584

__global__ void __launch_bounds__(256, 2)
conv1x1_mma(float* __restrict__ out) {
    extern __shared__ __half hsm[];
    uint32_t ss = smem_u32(hsm);
    int tid  = threadIdx.x;
    int wid  = tid >> 5, lane = tid & 31;
    int p0   = blockIdx.x * 128;
    int co0  = blockIdx.y * 128;
    int b    = blockIdx.z;

    int pm = (wid & 3) * 32;    // warp pixel base (2 m-tiles)
    int cn = (wid >> 2) * 64;   // warp cout base (8 n-tiles)
    int rr = lane >> 2, q = lane & 3;

    const __half* abase = g_t2h + ((size_t)b * NPIX + p0) * CC;
    const __half* wbase = g_w2h + (size_t)co0 * CC;

    auto stage = [&](int buf, int kb) {
        uint32_t da = ss + (uint32_t)buf * (X1_OPH * 2);
        uint32_t db = ss + (uint32_t)(2 * X1_OPH * 2) + (uint32_t)buf * (X1_OPH * 2);
#pragma unroll
        for (int j = 0; j < 2; ++j) {
            int ch  = tid + j * 256;          // 0..511
            int row = ch >> 2, c4 = ch & 3;   // row 0..127, 16B chunk 0..3
            uint32_t doff = (uint32_t)(row * (X1_TS * 2) + c4 * 16);
            cp16(da + doff, abase + (size_t)row * CC + kb * 32 + c4 * 8);
            cp16(db + doff, wbase + (size_t)row * CC + kb * 32 + c4 * 8);
        }
    };

    // ldmatrix per-lane bases
    uint32_t a_lbase = (uint32_t)((pm + (lane & 15)) * (X1_TS * 2) + (lane >> 4) * 16);
    int brow = ((lane >> 4) & 1) * 8 + (lane & 7);
    uint32_t b_lbase = (uint32_t)((cn + brow) * (X1_TS * 2) + ((lane >> 3) & 1) * 16);

    float acc[8][2][4];
#pragma unroll
    for (int nt = 0; nt < 8; ++nt)
#pragma unroll
        for (int mt = 0; mt < 2; ++mt)
#pragma unroll
            for (int i = 0; i < 4; ++i) acc[nt][mt][i] = 0.f;

    stage(0, 0);
    cp_commit();

    for (int kb = 0; kb < 8; ++kb) {
        int buf = kb & 1;
        __syncthreads();
        if (kb + 1 < 8) stage(buf ^ 1, kb + 1);
        cp_commit();
        cp_wait1();
        __syncthreads();

        uint32_t Ab = ss + (uint32_t)buf * (X1_OPH * 2) + a_lbase;
        uint32_t Bb = ss + (uint32_t)(2 * X1_OPH * 2) + (uint32_t)buf * (X1_OPH * 2) + b_lbase;

#pragma unroll
        for (int k16 = 0; k16 < 2; ++k16) {
            uint32_t kofs = (uint32_t)(k16 * 32);
            uint32_t afr[2][4], bfr[4][4];
#pragma unroll
            for (int mt = 0; mt < 2; ++mt)
                ldsm4(afr[mt], Ab + (uint32_t)(mt * 16 * (X1_TS * 2)) + kofs);
#pragma unroll
            for (int g16 = 0; g16 < 4; ++g16)
                ldsm4(bfr[g16], Bb + (uint32_t)(g16 * 16 * (X1_TS * 2)) + kofs);
#pragma unroll
            for (int nt = 0; nt < 8; ++nt)
#pragma unroll
                for (int mt = 0; mt < 2; ++mt)
                    mma16(acc[nt][mt], afr[mt], &bfr[nt >> 1][(nt & 1) * 2]);
        }
    }

    // epilogue: transpose acc through smem, then coalesced out = ska + D + bb2
    __syncthreads();                     // mainloop smem reads done
    float* tb = (float*)hsm;             // [co(128)][pix stride 132] = 16896 floats
    int q2 = q * 2;
#pragma unroll
    for (int nt = 0; nt < 8; ++nt) {
        int cw = cn + nt * 8 + q2;
#pragma unroll
        for (int mt = 0; mt < 2; ++mt) {
            int pw = pm + mt * 16 + rr;
            tb[cw * 132 + pw]           = acc[nt][mt][0];
            tb[(cw + 1) * 132 + pw]     = acc[nt][mt][1];
            tb[cw * 132 + pw + 8]       = acc[nt][mt][2];
            tb[(cw + 1) * 132 + pw + 8] = acc[nt][mt][3];
        }
    }
    __syncthreads();
#pragma unroll
    for (int j = 0; j < 16; ++j) {
        int lin = j * 1024 + tid * 4;
        int cw  = lin >> 7, px = lin & 127;
        int cg  = co0 + cw;
        float4 d = *(const float4*)&tb[cw * 132 + px];
        size_t a = (size_t)(b * CC + cg) * NPIX + p0 + px;
        float4 s = *(const float4*)(g_ska + a);
        float bb = g_bb2[cg];
        *(float4*)(out + a) = make_float4(s.x + d.x + bb, s.y + d.y + bb,
                                          s.z + d.z + bb, s.w + d.w + bb);
    }
}

extern "C" void kernel_launch(void* const* d_in, const int* in_sizes, int n_in,
                              void* d_out, int out_size) {
    const float* x   = (const float*)d_in[0];
    const float* dw  = (const float*)d_in[1];
    const float* roi = (const float*)d_in[2];
    const float* w1  = (const float*)d_in[3];
    const float* g1  = (const float*)d_in[4];
    const float* b1  = (const float*)d_in[5];
    const float* m1  = (const float*)d_in[6];
    const float* v1  = (const float*)d_in[7];
    const float* w2  = (const float*)d_in[8];
    const float* g2  = (const float*)d_in[9];
    const float* b2  = (const float*)d_in[10];
    const float* m2  = (const float*)d_in[11];
    const float* v2  = (const float*)d_in[12];
    float* out = (float*)d_out;

    cudaFuncSetAttribute(conv3_mma,   cudaFuncAttributeMaxDynamicSharedMemorySize, C3_SMEM);
    cudaFuncSetAttribute(conv1x1_mma, cudaFuncAttributeMaxDynamicSharedMemorySize, SM1X1);

    prep_bn<<<1, 256>>>(g1, b1, m1, v1, g2, b2, m2, v2);
    prep_w1h<<<288, 256>>>(w1);
    prep_w2h<<<256, 256>>>(w2);
    ska_kernel<<<dim3(HH / 2, BB * GG), 256>>>(x, dw, roi);
    conv3_mma<<<dim3(8, 8, BB * GG), 256, C3_SMEM>>>();
    conv1x1_mma<<<dim3(128, 2, BB), 256, SM1X1>>>(out);
}

// round 16
// speedup vs baseline: 1.0073x; 1.0073x over previous
#include <cuda_runtime.h>
#include <cuda_fp16.h>
#include <cstdint>

// Problem constants
#define BB   8
#define CC   256
#define HH   128
#define WW   128
#define GG   8       // ska groups (32 ch each)
#define NPIX 16384   // H*W
#define EPSV 1e-5f
#define HP   130     // spatially padded dim (1-px zero border)

// Scratch (device globals; allocation-free rule). Zero-initialized at load:
// g_ska2h's 1-pixel spatial border is never written -> stays zero (implicit pad).
__device__ __half g_skah[BB * CC * NPIX];               // raw SKA output (residual), planar fp16
__device__ __half g_ska2h[BB * GG * HP * HP * 32];      // ska*roi, channel-last, padded, fp16
__device__ __half g_t2h[BB * NPIX * CC];                // conv3 out, [b][pix][ci], fp16
__device__ __half g_w1h[GG * 9 * 32 * 32];              // w1*s1, [g][tap][co][cin], fp16
__device__ __half g_w2h[CC * CC];                       // w2*s2, [co][ci], fp16
__device__ float  g_s1[CC], g_bb1[CC], g_s2[CC], g_bb2[CC];

// ---------- cp.async helpers ----------
__device__ __forceinline__ void cp16(uint32_t dst, const void* src) {
    asm volatile("cp.async.cg.shared.global [%0], [%1], 16;" :: "r"(dst), "l"(src));
}
__device__ __forceinline__ void cp_commit() {
    asm volatile("cp.async.commit_group;");
}
__device__ __forceinline__ void cp_wait1() {
    asm volatile("cp.async.wait_group 1;");
}
__device__ __forceinline__ void cp_wait0() {
    asm volatile("cp.async.wait_group 0;");
}

__device__ __forceinline__ uint32_t smem_u32(const void* p) {
    uint32_t a;
    asm("{ .reg .u64 t; cvta.to.shared.u64 t, %1; cvt.u32.u64 %0, t; }" : "=r"(a) : "l"(p));
    return a;
}

__device__ __forceinline__ uint32_t h2bits(float a, float b) {
    __half2 h = __floats2half2_rn(a, b);
    return *reinterpret_cast<uint32_t*>(&h);
}

// ---------- mma.sync m16n8k16 fp16, fp32 accum ----------
__device__ __forceinline__ void mma16(float* c, const uint32_t* a, const uint32_t* b) {
    asm volatile(
        "mma.sync.aligned.m16n8k16.row.col.f32.f16.f16.f32 "
        "{%0,%1,%2,%3}, {%4,%5,%6,%7}, {%8,%9}, {%0,%1,%2,%3};"
        : "+f"(c[0]), "+f"(c[1]), "+f"(c[2]), "+f"(c[3])
        : "r"(a[0]), "r"(a[1]), "r"(a[2]), "r"(a[3]), "r"(b[0]), "r"(b[1]));
}

// ---------- ldmatrix x4 (b16, non-transposed) ----------
__device__ __forceinline__ void ldsm4(uint32_t* r, uint32_t addr) {
    asm volatile("ldmatrix.sync.aligned.m8n8.x4.shared.b16 {%0,%1,%2,%3}, [%4];"
                 : "=r"(r[0]), "=r"(r[1]), "=r"(r[2]), "=r"(r[3]) : "r"(addr));
}

// ---------- prep: fold BN params ----------
__global__ void prep_bn(const float* __restrict__ g1, const float* __restrict__ b1,
                        const float* __restrict__ m1, const float* __restrict__ v1,
                        const float* __restrict__ g2, const float* __restrict__ b2,
                        const float* __restrict__ m2, const float* __restrict__ v2) {
    int c = threadIdx.x;
    if (c < CC) {
        float i1 = g1[c] * rsqrtf(v1[c] + EPSV);
        g_s1[c]  = i1;
        g_bb1[c] = b1[c] - m1[c] * i1;
        float i2 = g2[c] * rsqrtf(v2[c] + EPSV);
        g_s2[c]  = i2;
        g_bb2[c] = b2[c] - m2[c] * i2;
    }
}

// ---------- prep: fold s1 into w1, fp16, [g][tap][co][cin] ----------
__global__ void prep_w1h(const float* __restrict__ w1) {
    int id = blockIdx.x * 256 + threadIdx.x;      // 73728 total
    int g  = id / 9216;
    int r  = id - g * 9216;
    int co = r / 288;
    int k  = r - co * 288;                        // cin*9 + tap
    int cin = k / 9, tap = k - cin * 9;
    g_w1h[g * 9216 + (tap * 32 + co) * 32 + cin] =
        __float2half_rn(w1[id] * g_s1[g * 32 + co]);
}

// ---------- prep: fold s2 into w2, fp16, [co][ci] ----------
__global__ void prep_w2h(const float* __restrict__ w2) {
    int i  = blockIdx.x * 256 + threadIdx.x;      // 65536 total
    g_w2h[i] = __float2half_rn(w2[i] * g_s2[i >> 8]);
}

// ---------- SKA: spatially-varying 3x3 aggregation (proven R14 structure) ----------
// grid (H/2, B*G), block 256: 2 output rows. Writes planar fp16 g_skah (residual)
// and channel-last padded fp16 g_ska2h (conv3 MMA input).
__global__ void ska_kernel(const float* __restrict__ x, const float* __restrict__ dw,
                           const float* __restrict__ roi) {
    int h0 = blockIdx.x * 2;
    int bg = blockIdx.y;                 // b*G + g
    int b  = bg >> 3, g = bg & 7;
    int tid = threadIdx.x;
    int hr = tid >> 7;                   // 0/1: which output row
    int w  = tid & 127;

    __shared__ float rows[4][130];
    if (tid < 4) {
        rows[tid][0]   = 0.f;
        rows[tid][129] = 0.f;
    }

    int h = h0 + hr;
    float dwv[9];
    const float* dp = dw + (size_t)bg * 9 * NPIX + h * WW + w;
#pragma unroll
    for (int k = 0; k < 9; ++k) dwv[k] = dp[k * NPIX];

    float rv = roi[b * NPIX + h * WW + w];

    const float* xb = x + (size_t)(b * CC + g * 32) * NPIX;
    __half* ob = g_skah + (size_t)(b * CC + g * 32) * NPIX + h * WW + w;

    float vals[32];
#pragma unroll
    for (int c = 0; c < 32; ++c) {
        __syncthreads();
        const float* xc = xb + c * NPIX;
#pragma unroll
        for (int j2 = 0; j2 < 2; ++j2) {
            int j  = hr * 2 + j2;
            int hh = h0 - 1 + j;
            rows[j][w + 1] = ((unsigned)hh < (unsigned)HH) ? xc[hh * WW + w] : 0.f;
        }
        __syncthreads();
        float acc = 0.f;
#pragma unroll
        for (int r = 0; r < 3; ++r)
#pragma unroll
            for (int kw = 0; kw < 3; ++kw)
                acc = fmaf(rows[hr + r][w + kw], dwv[r * 3 + kw], acc);
        ob[(size_t)c * NPIX] = __float2half_rn(acc);
        vals[c] = acc * rv;
    }

    // channel-last padded fp16 write (interior only; border stays zero)
    __half* o = g_ska2h + (((size_t)bg * HP + h + 1) * HP + (w + 1)) * 32;
    uint32_t pk[16];
#pragma unroll
    for (int t = 0; t < 16; ++t) pk[t] = h2bits(vals[2 * t], vals[2 * t + 1]);
#pragma unroll
    for (int t = 0; t < 4; ++t)
        ((uint4*)o)[t] = make_uint4(pk[t * 4], pk[t * 4 + 1], pk[t * 4 + 2], pk[t * 4 + 3]);
}

// ---------- grouped 3x3 conv: mma.sync fp16 + ldmatrix + BN + ReLU ----------
// grid (8,8,64): CTA = 16x16 pixel tile, one (b, group). K=288 fully smem-resident.
// 8 warps: warp = 2 pixel rows x 32 couts (2 mt x 4 nt), K=16/MMA.
// smem (halves, stride 40/row = 80B, conflict-free for ldmatrix 8-row phases).
#define C3_TS     40                              // halves per pixel row (pad 32->40)
#define C3_TILE_H (324 * C3_TS)                   // 12960 halves
#define C3_WT_H   (288 * C3_TS)                   // 11520 halves
#define C3_SMEM   ((C3_TILE_H + C3_WT_H) * 2)     // 48960 B

__global__ void __launch_bounds__(256, 3)
conv3_mma() {
    extern __shared__ __half hsm[];
    __half* tile = hsm;                  // [pix(18x18)][40]
    __half* wt   = hsm + C3_TILE_H;      // [tap*32+co][40]

    int bz  = blockIdx.z;
    int b   = bz >> 3, g = bz & 7;
    int px0 = blockIdx.x * 16, py0 = blockIdx.y * 16;
    int tid = threadIdx.x;
    int wid = tid >> 5, lane = tid & 31;
    int rr  = lane >> 2, q = lane & 3;

    // stage input tile: 324 px x 64B = 1296 chunks of 16B
    {
        const __half* sbase = g_ska2h + (((size_t)(b * GG + g) * HP + py0) * HP + px0) * 32;
        uint32_t ts = smem_u32(tile);
        for (int ch = tid; ch < 1296; ch += 256) {
            int pix = ch >> 2, c4 = ch & 3;
            int r = pix / 18, c = pix - r * 18;
            cp16(ts + (uint32_t)(pix * (C3_TS * 2) + c4 * 16),
                 sbase + ((size_t)r * HP + c) * 32 + c4 * 8);
        }
        // stage weights: 288 rows x 64B = 1152 chunks
        const __half* wsrc = g_w1h + g * 9216;
        uint32_t ws = smem_u32(wt);
        for (int ch = tid; ch < 1152; ch += 256) {
            int row = ch >> 2, c4 = ch & 3;
            cp16(ws + (uint32_t)(row * (C3_TS * 2) + c4 * 16),
                 wsrc + row * 32 + c4 * 8);
        }
        cp_commit();
    }

    // ldmatrix per-lane bases
    // A: lanes 0-15 -> m-rows (pixel cols) @k0; lanes 16-31 -> same rows @k0+16B
    uint32_t a_lbase = smem_u32(tile) + (uint32_t)((lane & 15) * (C3_TS * 2) + (lane >> 4) * 16);
    // B: lanes 0-7 -> co 0-7 @k0; 8-15 -> co 0-7 @k0+16B; 16-23 -> co 8-15 @k0; 24-31 -> co 8-15 @k0+16B
    int brow = ((lane >> 4) & 1) * 8 + (lane & 7);
    uint32_t b_lbase = smem_u32(wt) + (uint32_t)(brow * (C3_TS * 2) + ((lane >> 3) & 1) * 16);

    float acc[2][4][4];
#pragma unroll
    for (int mt = 0; mt < 2; ++mt)
#pragma unroll
        for (int nt = 0; nt < 4; ++nt)
#pragma unroll
            for (int i = 0; i < 4; ++i) acc[mt][nt][i] = 0.f;

    cp_wait0();
    __syncthreads();

#pragma unroll
    for (int tap = 0; tap < 9; ++tap) {
        int kh = tap / 3, kw = tap - kh * 3;
#pragma unroll
        for (int k16 = 0; k16 < 2; ++k16) {
            uint32_t kofs = (uint32_t)(k16 * 32);          // 16 halves = 32B
            uint32_t afr[2][4];
#pragma unroll
            for (int mt = 0; mt < 2; ++mt)
                ldsm4(afr[mt], a_lbase + (uint32_t)(((wid * 2 + mt + kh) * 18 + kw) * (C3_TS * 2)) + kofs);
            uint32_t bfr[2][4];   // [g16]: {nt0.b0, nt0.b1, nt1.b0, nt1.b1}
#pragma unroll
            for (int g16 = 0; g16 < 2; ++g16)
                ldsm4(bfr[g16], b_lbase + (uint32_t)((tap * 32 + g16 * 16) * (C3_TS * 2)) + kofs);
#pragma unroll
            for (int mt = 0; mt < 2; ++mt)
#pragma unroll
                for (int nt = 0; nt < 4; ++nt)
                    mma16(acc[mt][nt], afr[mt], &bfr[nt >> 1][(nt & 1) * 2]);
        }
    }

    // epilogue: BN + ReLU, transpose via smem -> coalesced fp16 channel-last STG
    __syncthreads();                     // mainloop reads of tile/wt done
    float* buf = (float*)hsm;            // [co(32)][pix stride 260] = 33280 B
    int j0 = q * 2;
#pragma unroll
    for (int mt = 0; mt < 2; ++mt) {
        int lp0 = (wid * 2 + mt) * 16 + rr;
#pragma unroll
        for (int nt = 0; nt < 4; ++nt) {
            int co = nt * 8 + j0;
            float bbA = g_bb1[g * 32 + co], bbB = g_bb1[g * 32 + co + 1];
            buf[co * 260 + lp0]           = fmaxf(acc[mt][nt][0] + bbA, 0.f);
            buf[(co + 1) * 260 + lp0]     = fmaxf(acc[mt][nt][1] + bbB, 0.f);
            buf[co * 260 + lp0 + 8]       = fmaxf(acc[mt][nt][2] + bbA, 0.f);
            buf[(co + 1) * 260 + lp0 + 8] = fmaxf(acc[mt][nt][3] + bbB, 0.f);
        }
    }
    __syncthreads();
    {
        int lp = tid;                    // local pixel 0..255
        int gp = (py0 + (lp >> 4)) * WW + px0 + (lp & 15);
        __half* o = g_t2h + ((size_t)b * NPIX + gp) * CC + g * 32;
        uint32_t pk[16];
#pragma unroll
        for (int t = 0; t < 16; ++t)
            pk[t] = h2bits(buf[(2 * t) * 260 + lp], buf[(2 * t + 1) * 260 + lp]);
#pragma unroll
        for (int t = 0; t < 4; ++t)
            ((uint4*)o)[t] = make_uint4(pk[t * 4], pk[t * 4 + 1], pk[t * 4 + 2], pk[t * 4 + 3]);
    }
}

// ---------- 1x1 conv: mma.sync fp16 GEMM + ldmatrix + BN + residual ----------
// grid (128, 2, B): block = 128 pix x 128 co, K=256 (8 cp.async chunks of 32).
// 8 warps: warp = 32 pix x 64 co = 2 mt x 8 nt, K=16/MMA.
#define X1_TS   40
#define X1_OPH  (128 * X1_TS)            // halves per buf per operand
#define SM1X1   67584

__global__ void __launch_bounds__(256, 2)
conv1x1_mma(float* __restrict__ out) {
    extern __shared__ __half hsm[];
    uint32_t ss = smem_u32(hsm);
    int tid  = threadIdx.x;
    int wid  = tid >> 5, lane = tid & 31;
    int p0   = blockIdx.x * 128;
    int co0  = blockIdx.y * 128;
    int b    = blockIdx.z;

    int pm = (wid & 3) * 32;    // warp pixel base (2 m-tiles)
    int cn = (wid >> 2) * 64;   // warp cout base (8 n-tiles)
    int rr = lane >> 2, q = lane & 3;

    const __half* abase = g_t2h + ((size_t)b * NPIX + p0) * CC;
    const __half* wbase = g_w2h + (size_t)co0 * CC;

    auto stage = [&](int buf, int kb) {
        uint32_t da = ss + (uint32_t)buf * (X1_OPH * 2);
        uint32_t db = ss + (uint32_t)(2 * X1_OPH * 2) + (uint32_t)buf * (X1_OPH * 2);
#pragma unroll
        for (int j = 0; j < 2; ++j) {
            int ch  = tid + j * 256;          // 0..511
            int row = ch >> 2, c4 = ch & 3;   // row 0..127, 16B chunk 0..3
            uint32_t doff = (uint32_t)(row * (X1_TS * 2) + c4 * 16);
            cp16(da + doff, abase + (size_t)row * CC + kb * 32 + c4 * 8);
            cp16(db + doff, wbase + (size_t)row * CC + kb * 32 + c4 * 8);
        }
    };

    // ldmatrix per-lane bases
    uint32_t a_lbase = (uint32_t)((pm + (lane & 15)) * (X1_TS * 2) + (lane >> 4) * 16);
    int brow = ((lane >> 4) & 1) * 8 + (lane & 7);
    uint32_t b_lbase = (uint32_t)((cn + brow) * (X1_TS * 2) + ((lane >> 3) & 1) * 16);

    float acc[8][2][4];
#pragma unroll
    for (int nt = 0; nt < 8; ++nt)
#pragma unroll
        for (int mt = 0; mt < 2; ++mt)
#pragma unroll
            for (int i = 0; i < 4; ++i) acc[nt][mt][i] = 0.f;

    stage(0, 0);
    cp_commit();

    for (int kb = 0; kb < 8; ++kb) {
        int buf = kb & 1;
        __syncthreads();
        if (kb + 1 < 8) stage(buf ^ 1, kb + 1);
        cp_commit();
        cp_wait1();
        __syncthreads();

        uint32_t Ab = ss + (uint32_t)buf * (X1_OPH * 2) + a_lbase;
        uint32_t Bb = ss + (uint32_t)(2 * X1_OPH * 2) + (uint32_t)buf * (X1_OPH * 2) + b_lbase;

#pragma unroll
        for (int k16 = 0; k16 < 2; ++k16) {
            uint32_t kofs = (uint32_t)(k16 * 32);
            uint32_t afr[2][4], bfr[4][4];
#pragma unroll
            for (int mt = 0; mt < 2; ++mt)
                ldsm4(afr[mt], Ab + (uint32_t)(mt * 16 * (X1_TS * 2)) + kofs);
#pragma unroll
            for (int g16 = 0; g16 < 4; ++g16)
                ldsm4(bfr[g16], Bb + (uint32_t)(g16 * 16 * (X1_TS * 2)) + kofs);
#pragma unroll
            for (int nt = 0; nt < 8; ++nt)
#pragma unroll
                for (int mt = 0; mt < 2; ++mt)
                    mma16(acc[nt][mt], afr[mt], &bfr[nt >> 1][(nt & 1) * 2]);
        }
    }

    // epilogue: transpose acc through smem, then coalesced out = ska + D + bb2
    __syncthreads();                     // mainloop smem reads done
    float* tb = (float*)hsm;             // [co(128)][pix stride 132] = 16896 floats
    int q2 = q * 2;
#pragma unroll
    for (int nt = 0; nt < 8; ++nt) {
        int cw = cn + nt * 8 + q2;
#pragma unroll
        for (int mt = 0; mt < 2; ++mt) {
            int pw = pm + mt * 16 + rr;
            tb[cw * 132 + pw]           = acc[nt][mt][0];
            tb[(cw + 1) * 132 + pw]     = acc[nt][mt][1];
            tb[cw * 132 + pw + 8]       = acc[nt][mt][2];
            tb[(cw + 1) * 132 + pw + 8] = acc[nt][mt][3];
        }
    }
    __syncthreads();
#pragma unroll
    for (int j = 0; j < 16; ++j) {
        int lin = j * 1024 + tid * 4;
        int cw  = lin >> 7, px = lin & 127;
        int cg  = co0 + cw;
        float4 d = *(const float4*)&tb[cw * 132 + px];
        size_t a = (size_t)(b * CC + cg) * NPIX + p0 + px;
        uint2 sraw = *(const uint2*)(g_skah + a);     // 4 fp16 residuals
        float2 s01 = __half22float2(*reinterpret_cast<__half2*>(&sraw.x));
        float2 s23 = __half22float2(*reinterpret_cast<__half2*>(&sraw.y));
        float bb = g_bb2[cg];
        *(float4*)(out + a) = make_float4(s01.x + d.x + bb, s01.y + d.y + bb,
                                          s23.x + d.z + bb, s23.y + d.w + bb);
    }
}

extern "C" void kernel_launch(void* const* d_in, const int* in_sizes, int n_in,
                              void* d_out, int out_size) {
    const float* x   = (const float*)d_in[0];
    const float* dw  = (const float*)d_in[1];
    const float* roi = (const float*)d_in[2];
    const float* w1  = (const float*)d_in[3];
    const float* g1  = (const float*)d_in[4];
    const float* b1  = (const float*)d_in[5];
    const float* m1  = (const float*)d_in[6];
    const float* v1  = (const float*)d_in[7];
    const float* w2  = (const float*)d_in[8];
    const float* g2  = (const float*)d_in[9];
    const float* b2  = (const float*)d_in[10];
    const float* m2  = (const float*)d_in[11];
    const float* v2  = (const float*)d_in[12];
    float* out = (float*)d_out;

    cudaFuncSetAttribute(conv3_mma,   cudaFuncAttributeMaxDynamicSharedMemorySize, C3_SMEM);
    cudaFuncSetAttribute(conv1x1_mma, cudaFuncAttributeMaxDynamicSharedMemorySize, SM1X1);

    prep_bn<<<1, 256>>>(g1, b1, m1, v1, g2, b2, m2, v2);
    prep_w1h<<<288, 256>>>(w1);
    prep_w2h<<<256, 256>>>(w2);
    ska_kernel<<<dim3(HH / 2, BB * GG), 256>>>(x, dw, roi);
    conv3_mma<<<dim3(8, 8, BB * GG), 256, C3_SMEM>>>();
    conv1x1_mma<<<dim3(128, 2, BB), 256, SM1X1>>>(out);
}

// round 17
// speedup vs baseline: 1.0651x; 1.0574x over previous
#include <cuda_runtime.h>
#include <cuda_fp16.h>
#include <cstdint>

// Problem constants
#define BB   8
#define CC   256
#define HH   128
#define WW   128
#define GG   8       // ska groups (32 ch each)
#define NPIX 16384   // H*W
#define EPSV 1e-5f
#define HP   130     // spatially padded dim (1-px zero border)

// Scratch (device globals; allocation-free rule). Zero-initialized at load:
// g_ska2h's 1-pixel spatial border is never written -> stays zero (implicit pad).
__device__ float  g_ska[BB * CC * NPIX];                // raw SKA output (residual), planar fp32
__device__ __half g_ska2h[BB * GG * HP * HP * 32];      // ska*roi, channel-last, padded, fp16
__device__ __half g_t2h[BB * NPIX * CC];                // conv3 out, [b][pix][ci], fp16
__device__ __half g_w1h[GG * 9 * 32 * 32];              // w1*s1, [g][tap][co][cin], fp16
__device__ __half g_w2h[CC * CC];                       // w2*s2, [co][ci], fp16
__device__ float  g_s1[CC], g_bb1[CC], g_s2[CC], g_bb2[CC];

// ---------- cp.async helpers ----------
__device__ __forceinline__ void cp16(uint32_t dst, const void* src) {
    asm volatile("cp.async.cg.shared.global [%0], [%1], 16;" :: "r"(dst), "l"(src));
}
__device__ __forceinline__ void cp_commit() {
    asm volatile("cp.async.commit_group;");
}
__device__ __forceinline__ void cp_wait1() {
    asm volatile("cp.async.wait_group 1;");
}
__device__ __forceinline__ void cp_wait0() {
    asm volatile("cp.async.wait_group 0;");
}

__device__ __forceinline__ uint32_t smem_u32(const void* p) {
    uint32_t a;
    asm("{ .reg .u64 t; cvta.to.shared.u64 t, %1; cvt.u32.u64 %0, t; }" : "=r"(a) : "l"(p));
    return a;
}

__device__ __forceinline__ uint32_t h2bits(float a, float b) {
    __half2 h = __floats2half2_rn(a, b);
    return *reinterpret_cast<uint32_t*>(&h);
}

// ---------- mma.sync m16n8k16 fp16, fp32 accum ----------
__device__ __forceinline__ void mma16(float* c, const uint32_t* a, const uint32_t* b) {
    asm volatile(
        "mma.sync.aligned.m16n8k16.row.col.f32.f16.f16.f32 "
        "{%0,%1,%2,%3}, {%4,%5,%6,%7}, {%8,%9}, {%0,%1,%2,%3};"
        : "+f"(c[0]), "+f"(c[1]), "+f"(c[2]), "+f"(c[3])
        : "r"(a[0]), "r"(a[1]), "r"(a[2]), "r"(a[3]), "r"(b[0]), "r"(b[1]));
}

// ---------- ldmatrix x4 (b16, non-transposed) ----------
__device__ __forceinline__ void ldsm4(uint32_t* r, uint32_t addr) {
    asm volatile("ldmatrix.sync.aligned.m8n8.x4.shared.b16 {%0,%1,%2,%3}, [%4];"
                 : "=r"(r[0]), "=r"(r[1]), "=r"(r[2]), "=r"(r[3]) : "r"(addr));
}

// ---------- prep: fold BN params ----------
__global__ void prep_bn(const float* __restrict__ g1, const float* __restrict__ b1,
                        const float* __restrict__ m1, const float* __restrict__ v1,
                        const float* __restrict__ g2, const float* __restrict__ b2,
                        const float* __restrict__ m2, const float* __restrict__ v2) {
    int c = threadIdx.x;
    if (c < CC) {
        float i1 = g1[c] * rsqrtf(v1[c] + EPSV);
        g_s1[c]  = i1;
        g_bb1[c] = b1[c] - m1[c] * i1;
        float i2 = g2[c] * rsqrtf(v2[c] + EPSV);
        g_s2[c]  = i2;
        g_bb2[c] = b2[c] - m2[c] * i2;
    }
}

// ---------- prep: fold s1 into w1, fp16, [g][tap][co][cin] ----------
__global__ void prep_w1h(const float* __restrict__ w1) {
    int id = blockIdx.x * 256 + threadIdx.x;      // 73728 total
    int g  = id / 9216;
    int r  = id - g * 9216;
    int co = r / 288;
    int k  = r - co * 288;                        // cin*9 + tap
    int cin = k / 9, tap = k - cin * 9;
    g_w1h[g * 9216 + (tap * 32 + co) * 32 + cin] =
        __float2half_rn(w1[id] * g_s1[g * 32 + co]);
}

// ---------- prep: fold s2 into w2, fp16, [co][ci] ----------
__global__ void prep_w2h(const float* __restrict__ w2) {
    int i  = blockIdx.x * 256 + threadIdx.x;      // 65536 total
    g_w2h[i] = __float2half_rn(w2[i] * g_s2[i >> 8]);
}

// ---------- SKA: spatially-varying 3x3 aggregation ----------
// grid (H/2, B*G), block 256: 2 output rows. TWO channels per barrier pair:
// 4 LDGs in flight, syncs halved vs R14.
__global__ void ska_kernel(const float* __restrict__ x, const float* __restrict__ dw,
                           const float* __restrict__ roi) {
    __shared__ float rows[2][4][130];    // [channel slab][row][w]
    int h0 = blockIdx.x * 2;
    int bg = blockIdx.y;                 // b*G + g
    int b  = bg >> 3, g = bg & 7;
    int tid = threadIdx.x;
    int hr = tid >> 7;                   // 0/1: which output row
    int w  = tid & 127;

    if (tid < 16) {                      // zero halo cols, both slabs
        int cc = tid >> 3, r = (tid >> 1) & 3, s = tid & 1;
        rows[cc][r][s * 129] = 0.f;
    }

    int h = h0 + hr;
    float dwv[9];
    const float* dp = dw + (size_t)bg * 9 * NPIX + h * WW + w;
#pragma unroll
    for (int k = 0; k < 9; ++k) dwv[k] = dp[k * NPIX];

    float rv = roi[b * NPIX + h * WW + w];

    const float* xb = x + (size_t)(b * CC + g * 32) * NPIX;
    float* ob = g_ska + (size_t)(b * CC + g * 32) * NPIX + h * WW + w;

    float vals[32];
#pragma unroll
    for (int c = 0; c < 32; c += 2) {
        __syncthreads();
        const float* xc0 = xb + (size_t)c * NPIX;
        const float* xc1 = xc0 + NPIX;
#pragma unroll
        for (int j2 = 0; j2 < 2; ++j2) {
            int j  = hr * 2 + j2;
            int hh = h0 - 1 + j;
            bool in = (unsigned)hh < (unsigned)HH;
            int off = hh * WW + w;
            rows[0][j][w + 1] = in ? xc0[off] : 0.f;
            rows[1][j][w + 1] = in ? xc1[off] : 0.f;
        }
        __syncthreads();
        float a0 = 0.f, a1 = 0.f;
#pragma unroll
        for (int r = 0; r < 3; ++r)
#pragma unroll
            for (int kw = 0; kw < 3; ++kw) {
                float wv = dwv[r * 3 + kw];
                a0 = fmaf(rows[0][hr + r][w + kw], wv, a0);
                a1 = fmaf(rows[1][hr + r][w + kw], wv, a1);
            }
        ob[(size_t)c * NPIX]       = a0;
        ob[(size_t)(c + 1) * NPIX] = a1;
        vals[c]     = a0 * rv;
        vals[c + 1] = a1 * rv;
    }

    // channel-last padded fp16 write (interior only; border stays zero)
    __half* o = g_ska2h + (((size_t)bg * HP + h + 1) * HP + (w + 1)) * 32;
    uint32_t pk[16];
#pragma unroll
    for (int t = 0; t < 16; ++t) pk[t] = h2bits(vals[2 * t], vals[2 * t + 1]);
#pragma unroll
    for (int t = 0; t < 4; ++t)
        ((uint4*)o)[t] = make_uint4(pk[t * 4], pk[t * 4 + 1], pk[t * 4 + 2], pk[t * 4 + 3]);
}

// ---------- grouped 3x3 conv: persistent mma.sync fp16 + ldmatrix ----------
// grid (8, 2, 64): CTA = one 16-px tile column x 4 row-tiles, one (b, group).
// Weights staged ONCE per CTA; tile staging double-buffered (overlaps compute).
// smem: wt[288][40]h + 2 x tile[324][40]h = 74880 B -> 3 CTAs/SM.
#define C3_TS     40                              // halves per row (pad 32->40)
#define C3_WT_H   (288 * C3_TS)                   // 11520 halves
#define C3_TILE_H (324 * C3_TS)                   // 12960 halves
#define C3_SMEM   ((C3_WT_H + 2 * C3_TILE_H) * 2) // 74880 B

__global__ void __launch_bounds__(256, 3)
conv3_mma() {
    extern __shared__ __half hsm[];
    __half* wt    = hsm;                 // [tap*32+co][40]
    __half* tiles = hsm + C3_WT_H;       // 2 buffers of [pix(18x18)][40]

    int bg  = blockIdx.z;
    int b   = bg >> 3, g = bg & 7;
    int px0 = blockIdx.x * 16;
    int t0  = blockIdx.y * 4;            // first of 4 row-tiles
    int tid = threadIdx.x;
    int wid = tid >> 5, lane = tid & 31;
    int rr  = lane >> 2, q = lane & 3;

    uint32_t ws  = smem_u32(wt);
    uint32_t ts0 = smem_u32(tiles);

    auto stage_tile = [&](int t, int buf) {
        const __half* sbase = g_ska2h + (((size_t)bg * HP + t * 16) * HP + px0) * 32;
        uint32_t d = ts0 + (uint32_t)buf * (C3_TILE_H * 2);
        for (int ch = tid; ch < 1296; ch += 256) {
            int pix = ch >> 2, c4 = ch & 3;
            int r = pix / 18, c = pix - r * 18;
            cp16(d + (uint32_t)(pix * 80 + c4 * 16),
                 sbase + ((size_t)r * HP + c) * 32 + c4 * 8);
        }
    };

    // stage weights (once) + first tile
    {
        const __half* wsrc = g_w1h + g * 9216;
        for (int ch = tid; ch < 1152; ch += 256) {
            int row = ch >> 2, c4 = ch & 3;
            cp16(ws + (uint32_t)(row * 80 + c4 * 16), wsrc + row * 32 + c4 * 8);
        }
        stage_tile(t0, 0);
        cp_commit();
    }

    // ldmatrix per-lane offsets
    uint32_t a_off   = (uint32_t)((lane & 15) * 80 + (lane >> 4) * 16);  // within tile buf
    int brow = ((lane >> 4) & 1) * 8 + (lane & 7);
    uint32_t b_lbase = ws + (uint32_t)(brow * 80 + ((lane >> 3) & 1) * 16);

    for (int tt = 0; tt < 4; ++tt) {
        int t   = t0 + tt;
        int buf = tt & 1;
        __syncthreads();                 // previous epilogue fully done
        if (tt + 1 < 4) {
            stage_tile(t + 1, buf ^ 1);
            cp_commit();
            cp_wait1();                  // current buf (and weights) ready
        } else {
            cp_wait0();
        }
        __syncthreads();

        float acc[2][4][4];
#pragma unroll
        for (int mt = 0; mt < 2; ++mt)
#pragma unroll
            for (int nt = 0; nt < 4; ++nt)
#pragma unroll
                for (int i = 0; i < 4; ++i) acc[mt][nt][i] = 0.f;

        uint32_t abase = ts0 + (uint32_t)buf * (C3_TILE_H * 2) + a_off;
#pragma unroll
        for (int tap = 0; tap < 9; ++tap) {
            int kh = tap / 3, kw = tap - kh * 3;
#pragma unroll
            for (int k16 = 0; k16 < 2; ++k16) {
                uint32_t kofs = (uint32_t)(k16 * 32);
                uint32_t afr[2][4];
#pragma unroll
                for (int mt = 0; mt < 2; ++mt)
                    ldsm4(afr[mt], abase + (uint32_t)(((wid * 2 + mt + kh) * 18 + kw) * 80) + kofs);
                uint32_t bfr[2][4];
#pragma unroll
                for (int g16 = 0; g16 < 2; ++g16)
                    ldsm4(bfr[g16], b_lbase + (uint32_t)((tap * 32 + g16 * 16) * 80) + kofs);
#pragma unroll
                for (int mt = 0; mt < 2; ++mt)
#pragma unroll
                    for (int nt = 0; nt < 4; ++nt)
                        mma16(acc[mt][nt], afr[mt], &bfr[nt >> 1][(nt & 1) * 2]);
            }
        }

        // epilogue: BN + ReLU, fp16 transpose via current tile buffer
        __syncthreads();                 // all warps done reading tile[buf]
        __half* ebuf = tiles + buf * C3_TILE_H;   // as [pix(256)][40] halves
        int j0 = q * 2;
#pragma unroll
        for (int mt = 0; mt < 2; ++mt) {
            int lp0 = (wid * 2 + mt) * 16 + rr;
#pragma unroll
            for (int nt = 0; nt < 4; ++nt) {
                int co = nt * 8 + j0;
                float bbA = g_bb1[g * 32 + co], bbB = g_bb1[g * 32 + co + 1];
                *(uint32_t*)&ebuf[lp0 * C3_TS + co] =
                    h2bits(fmaxf(acc[mt][nt][0] + bbA, 0.f), fmaxf(acc[mt][nt][1] + bbB, 0.f));
                *(uint32_t*)&ebuf[(lp0 + 8) * C3_TS + co] =
                    h2bits(fmaxf(acc[mt][nt][2] + bbA, 0.f), fmaxf(acc[mt][nt][3] + bbB, 0.f));
            }
        }
        __syncthreads();
        {
            int lp = tid;                // local pixel 0..255
            int gp = (t * 16 + (lp >> 4)) * WW + px0 + (lp & 15);
            __half* o = g_t2h + ((size_t)b * NPIX + gp) * CC + g * 32;
#pragma unroll
            for (int k = 0; k < 4; ++k)
                ((uint4*)o)[k] = *(const uint4*)&ebuf[lp * C3_TS + k * 8];
        }
    }
}

// ---------- 1x1 conv: mma.sync fp16 GEMM + ldmatrix + BN + residual ----------
// grid (128, 2, B): block = 128 pix x 128 co, K=256 (8 cp.async chunks of 32).
// 8 warps: warp = 32 pix x 64 co = 2 mt x 8 nt, K=16/MMA.
#define X1_TS   40
#define X1_OPH  (128 * X1_TS)            // halves per buf per operand
#define SM1X1   67584

__global__ void __launch_bounds__(256, 2)
conv1x1_mma(float* __restrict__ out) {
    extern __shared__ __half hsm[];
    uint32_t ss = smem_u32(hsm);
    int tid  = threadIdx.x;
    int wid  = tid >> 5, lane = tid & 31;
    int p0   = blockIdx.x * 128;
    int co0  = blockIdx.y * 128;
    int b    = blockIdx.z;

    int pm = (wid & 3) * 32;    // warp pixel base (2 m-tiles)
    int cn = (wid >> 2) * 64;   // warp cout base (8 n-tiles)
    int rr = lane >> 2, q = lane & 3;

    const __half* abase = g_t2h + ((size_t)b * NPIX + p0) * CC;
    const __half* wbase = g_w2h + (size_t)co0 * CC;

    auto stage = [&](int buf, int kb) {
        uint32_t da = ss + (uint32_t)buf * (X1_OPH * 2);
        uint32_t db = ss + (uint32_t)(2 * X1_OPH * 2) + (uint32_t)buf * (X1_OPH * 2);
#pragma unroll
        for (int j = 0; j < 2; ++j) {
            int ch  = tid + j * 256;          // 0..511
            int row = ch >> 2, c4 = ch & 3;   // row 0..127, 16B chunk 0..3
            uint32_t doff = (uint32_t)(row * (X1_TS * 2) + c4 * 16);
            cp16(da + doff, abase + (size_t)row * CC + kb * 32 + c4 * 8);
            cp16(db + doff, wbase + (size_t)row * CC + kb * 32 + c4 * 8);
        }
    };

    // ldmatrix per-lane bases
    uint32_t a_lbase = (uint32_t)((pm + (lane & 15)) * (X1_TS * 2) + (lane >> 4) * 16);
    int brow = ((lane >> 4) & 1) * 8 + (lane & 7);
    uint32_t b_lbase = (uint32_t)((cn + brow) * (X1_TS * 2) + ((lane >> 3) & 1) * 16);

    float acc[8][2][4];
#pragma unroll
    for (int nt = 0; nt < 8; ++nt)
#pragma unroll
        for (int mt = 0; mt < 2; ++mt)
#pragma unroll
            for (int i = 0; i < 4; ++i) acc[nt][mt][i] = 0.f;

    stage(0, 0);
    cp_commit();

    for (int kb = 0; kb < 8; ++kb) {
        int buf = kb & 1;
        __syncthreads();
        if (kb + 1 < 8) stage(buf ^ 1, kb + 1);
        cp_commit();
        cp_wait1();
        __syncthreads();

        uint32_t Ab = ss + (uint32_t)buf * (X1_OPH * 2) + a_lbase;
        uint32_t Bb = ss + (uint32_t)(2 * X1_OPH * 2) + (uint32_t)buf * (X1_OPH * 2) + b_lbase;

#pragma unroll
        for (int k16 = 0; k16 < 2; ++k16) {
            uint32_t kofs = (uint32_t)(k16 * 32);
            uint32_t afr[2][4], bfr[4][4];
#pragma unroll
            for (int mt = 0; mt < 2; ++mt)
                ldsm4(afr[mt], Ab + (uint32_t)(mt * 16 * (X1_TS * 2)) + kofs);
#pragma unroll
            for (int g16 = 0; g16 < 4; ++g16)
                ldsm4(bfr[g16], Bb + (uint32_t)(g16 * 16 * (X1_TS * 2)) + kofs);
#pragma unroll
            for (int nt = 0; nt < 8; ++nt)
#pragma unroll
                for (int mt = 0; mt < 2; ++mt)
                    mma16(acc[nt][mt], afr[mt], &bfr[nt >> 1][(nt & 1) * 2]);
        }
    }

    // epilogue: transpose acc through smem, then coalesced out = ska + D + bb2
    __syncthreads();                     // mainloop smem reads done
    float* tb = (float*)hsm;             // [co(128)][pix stride 132] = 16896 floats
    int q2 = q * 2;
#pragma unroll
    for (int nt = 0; nt < 8; ++nt) {
        int cw = cn + nt * 8 + q2;
#pragma unroll
        for (int mt = 0; mt < 2; ++mt) {
            int pw = pm + mt * 16 + rr;
            tb[cw * 132 + pw]           = acc[nt][mt][0];
            tb[(cw + 1) * 132 + pw]     = acc[nt][mt][1];
            tb[cw * 132 + pw + 8]       = acc[nt][mt][2];
            tb[(cw + 1) * 132 + pw + 8] = acc[nt][mt][3];
        }
    }
    __syncthreads();
#pragma unroll
    for (int j = 0; j < 16; ++j) {
        int lin = j * 1024 + tid * 4;
        int cw  = lin >> 7, px = lin & 127;
        int cg  = co0 + cw;
        float4 d = *(const float4*)&tb[cw * 132 + px];
        size_t a = (size_t)(b * CC + cg) * NPIX + p0 + px;
        float4 s = *(const float4*)(g_ska + a);
        float bb = g_bb2[cg];
        *(float4*)(out + a) = make_float4(s.x + d.x + bb, s.y + d.y + bb,
                                          s.z + d.z + bb, s.w + d.w + bb);
    }
}

extern "C" void kernel_launch(void* const* d_in, const int* in_sizes, int n_in,
                              void* d_out, int out_size) {
    const float* x   = (const float*)d_in[0];
    const float* dw  = (const float*)d_in[1];
    const float* roi = (const float*)d_in[2];
    const float* w1  = (const float*)d_in[3];
    const float* g1  = (const float*)d_in[4];
    const float* b1  = (const float*)d_in[5];
    const float* m1  = (const float*)d_in[6];
    const float* v1  = (const float*)d_in[7];
    const float* w2  = (const float*)d_in[8];
    const float* g2  = (const float*)d_in[9];
    const float* b2  = (const float*)d_in[10];
    const float* m2  = (const float*)d_in[11];
    const float* v2  = (const float*)d_in[12];
    float* out = (float*)d_out;

    cudaFuncSetAttribute(conv3_mma,   cudaFuncAttributeMaxDynamicSharedMemorySize, C3_SMEM);
    cudaFuncSetAttribute(conv1x1_mma, cudaFuncAttributeMaxDynamicSharedMemorySize, SM1X1);

    prep_bn<<<1, 256>>>(g1, b1, m1, v1, g2, b2, m2, v2);
    prep_w1h<<<288, 256>>>(w1);
    prep_w2h<<<256, 256>>>(w2);
    ska_kernel<<<dim3(HH / 2, BB * GG), 256>>>(x, dw, roi);
    conv3_mma<<<dim3(8, 2, BB * GG), 256, C3_SMEM>>>();
    conv1x1_mma<<<dim3(128, 2, BB), 256, SM1X1>>>(out);
}